// round 3
// baseline (speedup 1.0000x reference)
#include <cuda_runtime.h>

#define B_  4
#define T_  2048
#define D_  1024
#define H_  16
#define DK_ 64
#define M_  (B_*T_)   // 8192 rows

// Scratch (allocation rules forbid cudaMalloc; __device__ globals are the sanctioned path)
__device__ float g_q[(size_t)B_*H_*T_*DK_];   // (B,H,T,64)
__device__ float g_k[(size_t)B_*H_*T_*DK_];
__device__ float g_v[(size_t)B_*H_*T_*DK_];
__device__ float g_ctx[(size_t)M_*D_];        // (B,T,D)

__device__ __forceinline__ float neg_inf() { return __int_as_float(0xff800000u); }

// ---------------------------------------------------------------------------
// Tiled SGEMM: C[M,N] = A[M,K] * W[K,N] + bias;  BM=BN=128, BK=16, 256 thr, 8x8/thr
// MODE 0: store split-heads (B,H,T,64); MODE 1: store row-major (M,N)
// ---------------------------------------------------------------------------
template<int MODE>
__device__ __forceinline__ void gemm_body(
    const float* __restrict__ A, const float* __restrict__ W,
    const float* __restrict__ bias, float* __restrict__ out)
{
    __shared__ float As[16][132];   // [k][m], padded stride vs transpose-store conflicts
    __shared__ float Bs[16][128];   // [k][n]

    const int t  = threadIdx.x;
    const int tx = t & 15, ty = t >> 4;
    const int m0 = blockIdx.y * 128;
    const int n0 = blockIdx.x * 128;

    float acc[8][8];
#pragma unroll
    for (int i = 0; i < 8; i++)
#pragma unroll
        for (int j = 0; j < 8; j++) acc[i][j] = 0.f;

    for (int k0 = 0; k0 < D_; k0 += 16) {
        // A tile 128x16 (2 float4 / thread), transposed store into As[k][m]
#pragma unroll
        for (int i = 0; i < 2; i++) {
            int idx = t + i * 256;            // 0..511
            int row = idx >> 2;               // 0..127
            int c4  = (idx & 3) << 2;         // 0,4,8,12
            float4 a = *(const float4*)(A + (size_t)(m0 + row) * D_ + k0 + c4);
            As[c4 + 0][row] = a.x; As[c4 + 1][row] = a.y;
            As[c4 + 2][row] = a.z; As[c4 + 3][row] = a.w;
        }
        // B tile 16x128 (2 float4 / thread)
#pragma unroll
        for (int i = 0; i < 2; i++) {
            int idx = t + i * 256;
            int row = idx >> 5;               // 0..15
            int c4  = (idx & 31) << 2;        // 0..124
            *(float4*)&Bs[row][c4] =
                *(const float4*)(W + (size_t)(k0 + row) * D_ + n0 + c4);
        }
        __syncthreads();

#pragma unroll
        for (int k = 0; k < 16; k++) {
            float4 a0 = *(float4*)&As[k][ty * 8];
            float4 a1 = *(float4*)&As[k][ty * 8 + 4];
            float4 b0 = *(float4*)&Bs[k][tx * 8];
            float4 b1 = *(float4*)&Bs[k][tx * 8 + 4];
            float av[8] = {a0.x, a0.y, a0.z, a0.w, a1.x, a1.y, a1.z, a1.w};
            float bw[8] = {b0.x, b0.y, b0.z, b0.w, b1.x, b1.y, b1.z, b1.w};
#pragma unroll
            for (int i = 0; i < 8; i++)
#pragma unroll
                for (int j = 0; j < 8; j++) acc[i][j] += av[i] * bw[j];
        }
        __syncthreads();
    }

#pragma unroll
    for (int i = 0; i < 8; i++) {
        int m = m0 + ty * 8 + i;
#pragma unroll
        for (int j = 0; j < 8; j++) {
            int n = n0 + tx * 8 + j;
            float v = acc[i][j] + bias[n];
            if (MODE == 0) {
                int b  = m >> 11;          // /T_
                int tt = m & (T_ - 1);
                int h  = n >> 6;
                int dd = n & 63;
                out[(((size_t)(b * H_ + h) * T_ + tt) << 6) + dd] = v;
            } else {
                out[(size_t)m * D_ + n] = v;
            }
        }
    }
}

__global__ void __launch_bounds__(256) qkv_kernel(
    const float* __restrict__ x,
    const float* __restrict__ Wq, const float* __restrict__ bq,
    const float* __restrict__ Wk, const float* __restrict__ bk,
    const float* __restrict__ Wv, const float* __restrict__ bv)
{
    if      (blockIdx.z == 0) gemm_body<0>(x, Wq, bq, g_q);
    else if (blockIdx.z == 1) gemm_body<0>(x, Wk, bk, g_k);
    else                      gemm_body<0>(x, Wv, bv, g_v);
}

__global__ void __launch_bounds__(256) oproj_kernel(
    const float* __restrict__ Wo, const float* __restrict__ bo,
    float* __restrict__ out)
{
    gemm_body<1>(g_ctx, Wo, bo, out);
}

// ---------------------------------------------------------------------------
// Flash attention (causal): grid (T/64, B*H), 256 thr (8 warps x 8 query rows),
// lane owns output dims {2*lane, 2*lane+1}. Online softmax in registers.
// ---------------------------------------------------------------------------
__global__ void __launch_bounds__(256) attn_kernel()
{
    extern __shared__ float sm[];
    float* Qs = sm;                    // [64][64]  scaled Q
    float* Kt = sm + 64 * 64;          // [64][66]  K transposed (pad 66)
    float* Vs = Kt + 64 * 66;          // [64][64]
    float* Ps = Vs + 64 * 64;          // [64][64]

    const int t    = threadIdx.x;
    const int w    = t >> 5;
    const int lane = t & 31;
    const int qb   = blockIdx.x;       // query block
    const int bh   = blockIdx.y;       // b*H + h
    const size_t base = (size_t)bh * T_ * DK_;
    const float scale = 0.125f;        // 1/sqrt(64)

    // Load + scale Q tile (64x64), float4 coalesced
#pragma unroll
    for (int i = 0; i < 4; i++) {
        int idx4 = t + i * 256;        // 0..1023
        int r    = idx4 >> 4;
        int d4   = (idx4 & 15) << 2;
        float4 q = *(const float4*)(g_q + base + (size_t)(qb * 64 + r) * 64 + d4);
        q.x *= scale; q.y *= scale; q.z *= scale; q.w *= scale;
        *(float4*)&Qs[r * 64 + d4] = q;
    }

    const int r0 = w * 8;
    float m_i[8], l_i[8], acc0[8], acc1[8];
#pragma unroll
    for (int rr = 0; rr < 8; rr++) {
        m_i[rr] = neg_inf(); l_i[rr] = 0.f; acc0[rr] = 0.f; acc1[rr] = 0.f;
    }

    for (int kb = 0; kb <= qb; kb++) {
        __syncthreads();   // previous iteration's Ps/Vs reads done before overwrite
        // Load K (transposed) and V tiles
#pragma unroll
        for (int i = 0; i < 4; i++) {
            int idx4 = t + i * 256;
            int c    = idx4 >> 4;
            int d4   = (idx4 & 15) << 2;
            float4 kv = *(const float4*)(g_k + base + (size_t)(kb * 64 + c) * 64 + d4);
            Kt[(d4 + 0) * 66 + c] = kv.x;
            Kt[(d4 + 1) * 66 + c] = kv.y;
            Kt[(d4 + 2) * 66 + c] = kv.z;
            Kt[(d4 + 3) * 66 + c] = kv.w;
            *(float4*)&Vs[c * 64 + d4] =
                *(const float4*)(g_v + base + (size_t)(kb * 64 + c) * 64 + d4);
        }
        __syncthreads();

        // S = Q K^T : lane computes columns {2*lane, 2*lane+1} for 8 rows
        float s0[8], s1[8];
#pragma unroll
        for (int rr = 0; rr < 8; rr++) { s0[rr] = 0.f; s1[rr] = 0.f; }
#pragma unroll
        for (int d = 0; d < 64; d += 4) {
            float2 k0 = *(float2*)&Kt[(d + 0) * 66 + 2 * lane];
            float2 k1 = *(float2*)&Kt[(d + 1) * 66 + 2 * lane];
            float2 k2 = *(float2*)&Kt[(d + 2) * 66 + 2 * lane];
            float2 k3 = *(float2*)&Kt[(d + 3) * 66 + 2 * lane];
#pragma unroll
            for (int rr = 0; rr < 8; rr++) {
                float4 q = *(float4*)&Qs[(r0 + rr) * 64 + d];
                s0[rr] += q.x * k0.x + q.y * k1.x + q.z * k2.x + q.w * k3.x;
                s1[rr] += q.x * k0.y + q.y * k1.y + q.z * k2.y + q.w * k3.y;
            }
        }

        // Causal mask on the diagonal block
        if (kb == qb) {
            int c0 = 2 * lane, c1 = 2 * lane + 1;
#pragma unroll
            for (int rr = 0; rr < 8; rr++) {
                int r = r0 + rr;
                if (c0 > r) s0[rr] = neg_inf();
                if (c1 > r) s1[rr] = neg_inf();
            }
        }

        // Online softmax update, write P to smem (rows warp-private)
#pragma unroll
        for (int rr = 0; rr < 8; rr++) {
            float mx = fmaxf(s0[rr], s1[rr]);
#pragma unroll
            for (int off = 16; off > 0; off >>= 1)
                mx = fmaxf(mx, __shfl_xor_sync(0xffffffffu, mx, off));
            float m_new = fmaxf(m_i[rr], mx);
            float p0 = __expf(s0[rr] - m_new);
            float p1 = __expf(s1[rr] - m_new);
            float rs = p0 + p1;
#pragma unroll
            for (int off = 16; off > 0; off >>= 1)
                rs += __shfl_xor_sync(0xffffffffu, rs, off);
            float alpha = __expf(m_i[rr] - m_new);
            l_i[rr] = l_i[rr] * alpha + rs;
            m_i[rr] = m_new;
            acc0[rr] *= alpha; acc1[rr] *= alpha;
            *(float2*)&Ps[(r0 + rr) * 64 + 2 * lane] = make_float2(p0, p1);
        }
        // (warp-synchronous: Ps rows belong to this warp, no block sync needed)

        // O += P V : lane accumulates dims {2*lane, 2*lane+1}
#pragma unroll
        for (int j = 0; j < 64; j += 4) {
            float2 v0 = *(float2*)&Vs[(j + 0) * 64 + 2 * lane];
            float2 v1 = *(float2*)&Vs[(j + 1) * 64 + 2 * lane];
            float2 v2 = *(float2*)&Vs[(j + 2) * 64 + 2 * lane];
            float2 v3 = *(float2*)&Vs[(j + 3) * 64 + 2 * lane];
#pragma unroll
            for (int rr = 0; rr < 8; rr++) {
                float4 p = *(float4*)&Ps[(r0 + rr) * 64 + j];
                acc0[rr] += p.x * v0.x + p.y * v1.x + p.z * v2.x + p.w * v3.x;
                acc1[rr] += p.x * v0.y + p.y * v1.y + p.z * v2.y + p.w * v3.y;
            }
        }
    }

    // Epilogue: normalize, write ctx in (B,T,D)
    const int b = bh >> 4, h = bh & 15;
#pragma unroll
    for (int rr = 0; rr < 8; rr++) {
        float inv = 1.f / l_i[rr];
        int tt = qb * 64 + r0 + rr;
        size_t o = (size_t)(b * T_ + tt) * D_ + h * 64;
        *(float2*)&g_ctx[o + 2 * lane] = make_float2(acc0[rr] * inv, acc1[rr] * inv);
    }
}

// ---------------------------------------------------------------------------
extern "C" void kernel_launch(void* const* d_in, const int* in_sizes, int n_in,
                              void* d_out, int out_size)
{
    (void)in_sizes; (void)n_in; (void)out_size;
    const float* x  = (const float*)d_in[0];
    const float* Wq = (const float*)d_in[1];
    const float* bq = (const float*)d_in[2];
    const float* Wk = (const float*)d_in[3];
    const float* bk = (const float*)d_in[4];
    const float* Wv = (const float*)d_in[5];
    const float* bv = (const float*)d_in[6];
    const float* Wo = (const float*)d_in[7];
    const float* bo = (const float*)d_in[8];
    float* out = (float*)d_out;

    // QKV projections: 3 GEMMs in one launch via gridDim.z
    dim3 gq(D_ / 128, M_ / 128, 3);
    qkv_kernel<<<gq, 256>>>(x, Wq, bq, Wk, bk, Wv, bv);

    // Flash attention
    const int ATTN_SMEM = (64 * 64 + 64 * 66 + 64 * 64 + 64 * 64) * 4;  // 66048 B
    cudaFuncSetAttribute(attn_kernel,
                         cudaFuncAttributeMaxDynamicSharedMemorySize, ATTN_SMEM);
    attn_kernel<<<dim3(T_ / 64, B_ * H_), 256, ATTN_SMEM>>>();

    // Output projection
    oproj_kernel<<<dim3(D_ / 128, M_ / 128), 256>>>(Wo, bo, out);
}

// round 6
// speedup vs baseline: 5.1503x; 5.1503x over previous
#include <cuda_runtime.h>
#include <cstdint>

#define B_  4
#define T_  2048
#define D_  1024
#define H_  16
#define M_  (B_*T_)   // 8192

// Scratch (__device__ globals — allocation rules forbid cudaMalloc)
__device__ float g_q[(size_t)B_*H_*T_*64];   // (B,H,T,64)
__device__ float g_k[(size_t)B_*H_*T_*64];
__device__ float g_v[(size_t)B_*H_*T_*64];
__device__ float g_ctx[(size_t)M_*D_];       // (B,T,D)

__device__ __forceinline__ float neg_inf() { return __int_as_float(0xff800000u); }

__device__ __forceinline__ uint32_t f2tf(float f) {
    uint32_t u;
    asm("cvt.rna.tf32.f32 %0, %1;" : "=r"(u) : "f"(f));
    return u;
}

// D += A*B, m16n8k8 tf32.
// A frag regs: a0=(g,tig) a1=(g+8,tig) a2=(g,tig+4) a3=(g+8,tig+4)
// B frag regs: b0=(tig,g)  b1=(tig+4,g)
// C frag regs: c0=(g,2tig) c1=(g,2tig+1) c2=(g+8,2tig) c3=(g+8,2tig+1)
__device__ __forceinline__ void mma_tf32(float* d, const uint32_t* a, const uint32_t* b) {
    asm volatile(
        "mma.sync.aligned.m16n8k8.row.col.f32.tf32.tf32.f32 "
        "{%0,%1,%2,%3}, {%4,%5,%6,%7}, {%8,%9}, {%0,%1,%2,%3};"
        : "+f"(d[0]), "+f"(d[1]), "+f"(d[2]), "+f"(d[3])
        : "r"(a[0]), "r"(a[1]), "r"(a[2]), "r"(a[3]), "r"(b[0]), "r"(b[1]));
}

// ---------------------------------------------------------------------------
// tf32 tensor-core GEMM: C[M,1024] = A[M,1024]*W + bias
// BM=BN=128, BK=32; 8 warps (2x4), warp tile 64x32; reg-prefetch pipeline.
// MODE 0: store split-heads (B,H,T,64); MODE 1: row-major (M,1024)
// ---------------------------------------------------------------------------
#define AS_STRIDE 36    // 32 + 4 pad  -> frag loads conflict-free
#define BS_STRIDE 136   // 128 + 8 pad -> frag loads conflict-free

template<int MODE>
__device__ __forceinline__ void gemm_tf32(
    const float* __restrict__ A, const float* __restrict__ W,
    const float* __restrict__ bias, float* __restrict__ out)
{
    __shared__ uint32_t As[128 * AS_STRIDE];
    __shared__ uint32_t Bs[32  * BS_STRIDE];

    const int t    = threadIdx.x;
    const int lane = t & 31;
    const int w    = t >> 5;
    const int g    = lane >> 2;
    const int tig  = lane & 3;
    const int wm   = (w >> 2) * 64;   // warp m-offset in block
    const int wn   = (w & 3) * 32;    // warp n-offset
    const int m0   = blockIdx.y * 128;
    const int n0   = blockIdx.x * 128;

    const int arow = t >> 3, ac4 = (t & 7) * 4;    // A tile loader coords
    const int brow = t >> 5, bc4 = (t & 31) * 4;   // B tile loader coords

    float acc[4][4][4];
#pragma unroll
    for (int mt = 0; mt < 4; mt++)
#pragma unroll
        for (int nt = 0; nt < 4; nt++)
#pragma unroll
            for (int i = 0; i < 4; i++) acc[mt][nt][i] = 0.f;

    float4 ra[4], rb[4];

#pragma unroll
    for (int i = 0; i < 4; i++)
        ra[i] = *(const float4*)(A + (size_t)(m0 + arow + i * 32) * D_ + ac4);
#pragma unroll
    for (int i = 0; i < 4; i++)
        rb[i] = *(const float4*)(W + (size_t)(brow + i * 8) * D_ + n0 + bc4);

#pragma unroll
    for (int i = 0; i < 4; i++) {
        uint32_t* p = &As[(arow + i * 32) * AS_STRIDE + ac4];
        p[0] = f2tf(ra[i].x); p[1] = f2tf(ra[i].y); p[2] = f2tf(ra[i].z); p[3] = f2tf(ra[i].w);
        uint32_t* q = &Bs[(brow + i * 8) * BS_STRIDE + bc4];
        q[0] = f2tf(rb[i].x); q[1] = f2tf(rb[i].y); q[2] = f2tf(rb[i].z); q[3] = f2tf(rb[i].w);
    }
    __syncthreads();

    for (int kt = 0; kt < 32; kt++) {
        const int nk = (kt + 1) * 32;
        if (kt < 31) {
#pragma unroll
            for (int i = 0; i < 4; i++)
                ra[i] = *(const float4*)(A + (size_t)(m0 + arow + i * 32) * D_ + nk + ac4);
#pragma unroll
            for (int i = 0; i < 4; i++)
                rb[i] = *(const float4*)(W + (size_t)(nk + brow + i * 8) * D_ + n0 + bc4);
        }

#pragma unroll
        for (int kk = 0; kk < 4; kk++) {
            const int k = kk * 8;
            uint32_t a[4][4], b[4][2];
#pragma unroll
            for (int mt = 0; mt < 4; mt++) {
                const int r = wm + mt * 16 + g;
                a[mt][0] = As[r * AS_STRIDE + k + tig];
                a[mt][1] = As[(r + 8) * AS_STRIDE + k + tig];
                a[mt][2] = As[r * AS_STRIDE + k + tig + 4];
                a[mt][3] = As[(r + 8) * AS_STRIDE + k + tig + 4];
            }
#pragma unroll
            for (int nt = 0; nt < 4; nt++) {
                const int c = wn + nt * 8 + g;
                b[nt][0] = Bs[(k + tig) * BS_STRIDE + c];
                b[nt][1] = Bs[(k + tig + 4) * BS_STRIDE + c];
            }
#pragma unroll
            for (int mt = 0; mt < 4; mt++)
#pragma unroll
                for (int nt = 0; nt < 4; nt++)
                    mma_tf32(acc[mt][nt], a[mt], b[nt]);
        }

        __syncthreads();
        if (kt < 31) {
#pragma unroll
            for (int i = 0; i < 4; i++) {
                uint32_t* p = &As[(arow + i * 32) * AS_STRIDE + ac4];
                p[0] = f2tf(ra[i].x); p[1] = f2tf(ra[i].y); p[2] = f2tf(ra[i].z); p[3] = f2tf(ra[i].w);
                uint32_t* q = &Bs[(brow + i * 8) * BS_STRIDE + bc4];
                q[0] = f2tf(rb[i].x); q[1] = f2tf(rb[i].y); q[2] = f2tf(rb[i].z); q[3] = f2tf(rb[i].w);
            }
            __syncthreads();
        }
    }

    // Epilogue
#pragma unroll
    for (int mt = 0; mt < 4; mt++) {
        const int r = m0 + wm + mt * 16 + g;
#pragma unroll
        for (int nt = 0; nt < 4; nt++) {
            const int c = n0 + wn + nt * 8 + 2 * tig;
            const float b0 = bias[c], b1 = bias[c + 1];
            float2 v0 = make_float2(acc[mt][nt][0] + b0, acc[mt][nt][1] + b1);  // row r
            float2 v1 = make_float2(acc[mt][nt][2] + b0, acc[mt][nt][3] + b1);  // row r+8
            if (MODE == 0) {
                const int h = c >> 6, dd = c & 63;
                const int b0i = r >> 11, tt0 = r & (T_ - 1);
                *(float2*)&out[(((size_t)(b0i * H_ + h) * T_ + tt0) << 6) + dd] = v0;
                const int r1 = r + 8;
                const int b1i = r1 >> 11, tt1 = r1 & (T_ - 1);
                *(float2*)&out[(((size_t)(b1i * H_ + h) * T_ + tt1) << 6) + dd] = v1;
            } else {
                *(float2*)&out[(size_t)r * D_ + c] = v0;
                *(float2*)&out[(size_t)(r + 8) * D_ + c] = v1;
            }
        }
    }
}

__global__ void __launch_bounds__(256) qkv_kernel(
    const float* __restrict__ x,
    const float* __restrict__ Wq, const float* __restrict__ bq,
    const float* __restrict__ Wk, const float* __restrict__ bk,
    const float* __restrict__ Wv, const float* __restrict__ bv)
{
    if      (blockIdx.z == 0) gemm_tf32<0>(x, Wq, bq, g_q);
    else if (blockIdx.z == 1) gemm_tf32<0>(x, Wk, bk, g_k);
    else                      gemm_tf32<0>(x, Wv, bv, g_v);
}

__global__ void __launch_bounds__(256) oproj_kernel(
    const float* __restrict__ Wo, const float* __restrict__ bo,
    float* __restrict__ out)
{
    gemm_tf32<1>(g_ctx, Wo, bo, out);
}

// ---------------------------------------------------------------------------
// Flash attention, tf32 MMA. Block: 128 queries x one (b,h); 8 warps,
// warp owns 16 query rows. KV tiles of 64 keys. Online softmax in registers.
// smem: Ps[128][68] (doubles as Q staging), Ks[64][68], Vs[64][72]  (70656 B)
// ---------------------------------------------------------------------------
#define PS_STRIDE 68
#define KS_STRIDE 68
#define VS_STRIDE 72

__global__ void __launch_bounds__(256) attn_kernel()
{
    extern __shared__ uint32_t smb[];
    uint32_t* Ps = smb;                      // 128*68
    uint32_t* Ks = smb + 128 * PS_STRIDE;    // 64*68
    uint32_t* Vs = Ks  + 64 * KS_STRIDE;     // 64*72
    float*    Qf = (float*)smb;              // Q staging view (same region as Ps)

    const int t    = threadIdx.x;
    const int lane = t & 31;
    const int w    = t >> 5;
    const int g    = lane >> 2;
    const int tig  = lane & 3;
    const int qb   = blockIdx.x;
    const int bh   = blockIdx.y;
    const size_t base = (size_t)bh * T_ * 64;
    const int pr   = w * 16 + g;            // warp-local P/Q row (lane's first)
    const int qr   = qb * 128 + pr;         // global query row

    // Stage Q (scaled) then gather fragments into registers
#pragma unroll
    for (int i = 0; i < 8; i++) {
        const int idx4 = t + i * 256;            // 0..2047 float4s
        const int r = idx4 >> 4, d4 = (idx4 & 15) * 4;
        float4 q = *(const float4*)(g_q + base + (size_t)(qb * 128 + r) * 64 + d4);
        float* p = &Qf[r * PS_STRIDE + d4];
        p[0] = q.x * 0.125f; p[1] = q.y * 0.125f; p[2] = q.z * 0.125f; p[3] = q.w * 0.125f;
    }
    __syncthreads();

    uint32_t qa[8][4];
#pragma unroll
    for (int kk = 0; kk < 8; kk++) {
        const int d = kk * 8;
        qa[kk][0] = f2tf(Qf[pr * PS_STRIDE + d + tig]);
        qa[kk][1] = f2tf(Qf[(pr + 8) * PS_STRIDE + d + tig]);
        qa[kk][2] = f2tf(Qf[pr * PS_STRIDE + d + tig + 4]);
        qa[kk][3] = f2tf(Qf[(pr + 8) * PS_STRIDE + d + tig + 4]);
    }
    // Ps region is only rewritten by this warp for its own rows -> no block sync needed.

    float o[8][4];
#pragma unroll
    for (int nt = 0; nt < 8; nt++)
#pragma unroll
        for (int i = 0; i < 4; i++) o[nt][i] = 0.f;
    float m0r = neg_inf(), m1r = neg_inf(), l0 = 0.f, l1 = 0.f;

    const int kbmax = 2 * qb + 1;
    for (int kb = 0; kb <= kbmax; kb++) {
        __syncthreads();   // previous iteration's Ks/Vs reads complete
        // Load K,V tiles (64x64 each), tf32-convert on store
#pragma unroll
        for (int i = 0; i < 4; i++) {
            const int idx4 = t + i * 256;        // 0..1023
            const int r = idx4 >> 4, d4 = (idx4 & 15) * 4;
            float4 kv = *(const float4*)(g_k + base + (size_t)(kb * 64 + r) * 64 + d4);
            uint32_t* pk = &Ks[r * KS_STRIDE + d4];
            pk[0] = f2tf(kv.x); pk[1] = f2tf(kv.y); pk[2] = f2tf(kv.z); pk[3] = f2tf(kv.w);
            float4 vv = *(const float4*)(g_v + base + (size_t)(kb * 64 + r) * 64 + d4);
            uint32_t* pv = &Vs[r * VS_STRIDE + d4];
            pv[0] = f2tf(vv.x); pv[1] = f2tf(vv.y); pv[2] = f2tf(vv.z); pv[3] = f2tf(vv.w);
        }
        __syncthreads();

        // S = Q K^T  (warp: 16 x 64)
        float s[8][4];
#pragma unroll
        for (int nt = 0; nt < 8; nt++)
#pragma unroll
            for (int i = 0; i < 4; i++) s[nt][i] = 0.f;
#pragma unroll
        for (int kk = 0; kk < 8; kk++) {
            const int d = kk * 8;
#pragma unroll
            for (int nt = 0; nt < 8; nt++) {
                uint32_t b[2];
                b[0] = Ks[(nt * 8 + g) * KS_STRIDE + d + tig];
                b[1] = Ks[(nt * 8 + g) * KS_STRIDE + d + tig + 4];
                mma_tf32(s[nt], qa[kk], b);
            }
        }

        // Causal mask (only the up-to-2 diagonal key blocks need it)
        if (kb >= 2 * qb) {
            const int r0g = qr, r1g = qr + 8;
#pragma unroll
            for (int nt = 0; nt < 8; nt++) {
                const int j0 = kb * 64 + nt * 8 + 2 * tig;
                if (j0 > r0g)     s[nt][0] = neg_inf();
                if (j0 + 1 > r0g) s[nt][1] = neg_inf();
                if (j0 > r1g)     s[nt][2] = neg_inf();
                if (j0 + 1 > r1g) s[nt][3] = neg_inf();
            }
        }

        // Online softmax (rows g and g+8; 4-lane shfl groups share a row)
        float mx0 = neg_inf(), mx1 = neg_inf();
#pragma unroll
        for (int nt = 0; nt < 8; nt++) {
            mx0 = fmaxf(mx0, fmaxf(s[nt][0], s[nt][1]));
            mx1 = fmaxf(mx1, fmaxf(s[nt][2], s[nt][3]));
        }
        mx0 = fmaxf(mx0, __shfl_xor_sync(0xffffffffu, mx0, 1));
        mx0 = fmaxf(mx0, __shfl_xor_sync(0xffffffffu, mx0, 2));
        mx1 = fmaxf(mx1, __shfl_xor_sync(0xffffffffu, mx1, 1));
        mx1 = fmaxf(mx1, __shfl_xor_sync(0xffffffffu, mx1, 2));

        const float mn0 = fmaxf(m0r, mx0), mn1 = fmaxf(m1r, mx1);
        const float a0 = __expf(m0r - mn0), a1 = __expf(m1r - mn1);
        m0r = mn0; m1r = mn1;

        float rs0 = 0.f, rs1 = 0.f;
#pragma unroll
        for (int nt = 0; nt < 8; nt++) {
            s[nt][0] = __expf(s[nt][0] - mn0);
            s[nt][1] = __expf(s[nt][1] - mn0);
            s[nt][2] = __expf(s[nt][2] - mn1);
            s[nt][3] = __expf(s[nt][3] - mn1);
            rs0 += s[nt][0] + s[nt][1];
            rs1 += s[nt][2] + s[nt][3];
        }
        rs0 += __shfl_xor_sync(0xffffffffu, rs0, 1);
        rs0 += __shfl_xor_sync(0xffffffffu, rs0, 2);
        rs1 += __shfl_xor_sync(0xffffffffu, rs1, 1);
        rs1 += __shfl_xor_sync(0xffffffffu, rs1, 2);
        l0 = l0 * a0 + rs0;
        l1 = l1 * a1 + rs1;

#pragma unroll
        for (int nt = 0; nt < 8; nt++) {
            o[nt][0] *= a0; o[nt][1] *= a0;
            o[nt][2] *= a1; o[nt][3] *= a1;
        }

        // P -> smem (tf32), warp-private rows
#pragma unroll
        for (int nt = 0; nt < 8; nt++) {
            uint32_t* p0 = &Ps[pr * PS_STRIDE + nt * 8 + 2 * tig];
            p0[0] = f2tf(s[nt][0]); p0[1] = f2tf(s[nt][1]);
            uint32_t* p1 = &Ps[(pr + 8) * PS_STRIDE + nt * 8 + 2 * tig];
            p1[0] = f2tf(s[nt][2]); p1[1] = f2tf(s[nt][3]);
        }
        __syncwarp();

        // O += P V
#pragma unroll
        for (int kk = 0; kk < 8; kk++) {
            const int j = kk * 8;
            uint32_t pa[4];
            pa[0] = Ps[pr * PS_STRIDE + j + tig];
            pa[1] = Ps[(pr + 8) * PS_STRIDE + j + tig];
            pa[2] = Ps[pr * PS_STRIDE + j + tig + 4];
            pa[3] = Ps[(pr + 8) * PS_STRIDE + j + tig + 4];
#pragma unroll
            for (int nt = 0; nt < 8; nt++) {
                uint32_t b[2];
                b[0] = Vs[(j + tig) * VS_STRIDE + nt * 8 + g];
                b[1] = Vs[(j + tig + 4) * VS_STRIDE + nt * 8 + g];
                mma_tf32(o[nt], pa, b);
            }
        }
    }

    // Epilogue: normalize + write ctx (B,T,D)
    const int bb = bh >> 4, h = bh & 15;
    const float i0 = 1.f / l0, i1 = 1.f / l1;
#pragma unroll
    for (int nt = 0; nt < 8; nt++) {
        const int d = h * 64 + nt * 8 + 2 * tig;
        *(float2*)&g_ctx[(size_t)(bb * T_ + qr) * D_ + d] =
            make_float2(o[nt][0] * i0, o[nt][1] * i0);
        *(float2*)&g_ctx[(size_t)(bb * T_ + qr + 8) * D_ + d] =
            make_float2(o[nt][2] * i1, o[nt][3] * i1);
    }
}

// ---------------------------------------------------------------------------
extern "C" void kernel_launch(void* const* d_in, const int* in_sizes, int n_in,
                              void* d_out, int out_size)
{
    (void)in_sizes; (void)n_in; (void)out_size;
    const float* x  = (const float*)d_in[0];
    const float* Wq = (const float*)d_in[1];
    const float* bq = (const float*)d_in[2];
    const float* Wk = (const float*)d_in[3];
    const float* bk = (const float*)d_in[4];
    const float* Wv = (const float*)d_in[5];
    const float* bv = (const float*)d_in[6];
    const float* Wo = (const float*)d_in[7];
    const float* bo = (const float*)d_in[8];
    float* out = (float*)d_out;

    dim3 gq(D_ / 128, M_ / 128, 3);
    qkv_kernel<<<gq, 256>>>(x, Wq, bq, Wk, bk, Wv, bv);

    const int ATTN_SMEM = (128 * PS_STRIDE + 64 * KS_STRIDE + 64 * VS_STRIDE) * 4; // 70656
    cudaFuncSetAttribute(attn_kernel,
                         cudaFuncAttributeMaxDynamicSharedMemorySize, ATTN_SMEM);
    attn_kernel<<<dim3(T_ / 128, B_ * H_), 256, ATTN_SMEM>>>();

    oproj_kernel<<<dim3(D_ / 128, M_ / 128), 256>>>(Wo, bo, out);
}

// round 10
// speedup vs baseline: 7.6072x; 1.4770x over previous
#include <cuda_runtime.h>
#include <cuda_fp16.h>
#include <cstdint>

#define B_  4
#define T_  2048
#define D_  1024
#define H_  16
#define M_  (B_*T_)   // 8192

// Scratch (__device__ globals — allocation rules forbid cudaMalloc)
__device__ float  g_q[(size_t)B_*H_*T_*64];   // (B,H,T,64)
__device__ float  g_k[(size_t)B_*H_*T_*64];
__device__ float  g_v[(size_t)B_*H_*T_*64];
__device__ float  g_ctx[(size_t)M_*D_];       // (B,T,D)
__device__ __half g_wth[(size_t)4*D_*D_];     // W^T in fp16: [4][N][K]

__device__ __forceinline__ float neg_inf() { return __int_as_float(0xff800000u); }

__device__ __forceinline__ uint32_t packh2(float x, float y) {
    __half2 h = __floats2half2_rn(x, y);   // x -> lo, y -> hi
    return *(uint32_t*)&h;
}

// D += A*B, m16n8k16 fp16 (fp32 accum).
// A frag: a0=(g,2tig..+1) a1=(g+8,..) a2=(g,2tig+8..) a3=(g+8,2tig+8..)
// B frag: b0=(k=2tig..+1, n=g) b1=(k=2tig+8..+9, n=g)
// C frag: c0=(g,2tig) c1=(g,2tig+1) c2=(g+8,2tig) c3=(g+8,2tig+1)
__device__ __forceinline__ void mma_f16(float* d, const uint32_t* a, const uint32_t* b) {
    asm volatile(
        "mma.sync.aligned.m16n8k16.row.col.f32.f16.f16.f32 "
        "{%0,%1,%2,%3}, {%4,%5,%6,%7}, {%8,%9}, {%0,%1,%2,%3};"
        : "+f"(d[0]), "+f"(d[1]), "+f"(d[2]), "+f"(d[3])
        : "r"(a[0]), "r"(a[1]), "r"(a[2]), "r"(a[3]), "r"(b[0]), "r"(b[1]));
}

// ---------------------------------------------------------------------------
// Weight transpose + fp16 round: g_wth[g][n][k] = half(W_g[k][n])
// ---------------------------------------------------------------------------
__global__ void __launch_bounds__(256) transpose_w(
    const float* __restrict__ W0, const float* __restrict__ W1,
    const float* __restrict__ W2, const float* __restrict__ W3)
{
    __shared__ float tile[32][33];
    const float* W = blockIdx.z == 0 ? W0 : blockIdx.z == 1 ? W1 : blockIdx.z == 2 ? W2 : W3;
    __half* out = g_wth + (size_t)blockIdx.z * D_ * D_;
    const int k0 = blockIdx.x * 32, n0 = blockIdx.y * 32;
    const int tx = threadIdx.x & 31, ty = threadIdx.x >> 5;
#pragma unroll
    for (int i = 0; i < 32; i += 8)
        tile[ty + i][tx] = W[(size_t)(k0 + ty + i) * D_ + n0 + tx];
    __syncthreads();
#pragma unroll
    for (int i = 0; i < 32; i += 8)
        out[(size_t)(n0 + ty + i) * D_ + k0 + tx] = __float2half_rn(tile[tx][ty + i]);
}

// ---------------------------------------------------------------------------
// fp16 tensor-core GEMM: C[M,1024] = A[M,1024]*W + bias
// BM=BN=128, BK=32; 8 warps (2x4), warp tile 64x32; reg-prefetch pipeline.
// As: [m][k] halves stride 40;  Bs: [n][k] halves stride 40 (from g_wth).
// MODE 0: store split-heads (B,H,T,64); MODE 1: row-major (M,1024)
// ---------------------------------------------------------------------------
#define AS_H 40
#define BS_H 40

template<int MODE>
__device__ __forceinline__ void gemm_f16(
    const float* __restrict__ A, const __half* __restrict__ Wt,
    const float* __restrict__ bias, float* __restrict__ out)
{
    __shared__ __half As[128 * AS_H];
    __shared__ __half Bs[128 * BS_H];

    const int t    = threadIdx.x;
    const int lane = t & 31;
    const int w    = t >> 5;
    const int g    = lane >> 2;
    const int tig  = lane & 3;
    const int wm   = (w >> 2) * 64;
    const int wn   = (w & 3) * 32;
    const int m0   = blockIdx.y * 128;
    const int n0   = blockIdx.x * 128;

    const int arow = t >> 3, ac4 = (t & 7) * 4;     // A loader: 128 rows x 32 f32
    const int brow = t >> 2, bseg = (t & 3) * 8;    // B loader: 128 rows x 32 h

    float acc[4][4][4];
#pragma unroll
    for (int mt = 0; mt < 4; mt++)
#pragma unroll
        for (int nt = 0; nt < 4; nt++)
#pragma unroll
            for (int i = 0; i < 4; i++) acc[mt][nt][i] = 0.f;

    float4 ra[4];
    uint4  rb[2];

#pragma unroll
    for (int i = 0; i < 4; i++)
        ra[i] = *(const float4*)(A + (size_t)(m0 + arow + i * 32) * D_ + ac4);
#pragma unroll
    for (int i = 0; i < 2; i++)
        rb[i] = *(const uint4*)(Wt + (size_t)(n0 + brow + i * 64) * D_ + bseg);

#pragma unroll
    for (int i = 0; i < 4; i++) {
        uint2 p = make_uint2(packh2(ra[i].x, ra[i].y), packh2(ra[i].z, ra[i].w));
        *(uint2*)&As[(arow + i * 32) * AS_H + ac4] = p;
    }
#pragma unroll
    for (int i = 0; i < 2; i++)
        *(uint4*)&Bs[(brow + i * 64) * BS_H + bseg] = rb[i];
    __syncthreads();

    for (int kt = 0; kt < 32; kt++) {
        const int nk = (kt + 1) * 32;
        if (kt < 31) {
#pragma unroll
            for (int i = 0; i < 4; i++)
                ra[i] = *(const float4*)(A + (size_t)(m0 + arow + i * 32) * D_ + nk + ac4);
#pragma unroll
            for (int i = 0; i < 2; i++)
                rb[i] = *(const uint4*)(Wt + (size_t)(n0 + brow + i * 64) * D_ + nk + bseg);
        }

#pragma unroll
        for (int kk = 0; kk < 2; kk++) {
            const int k = kk * 16;
            uint32_t a[4][4], b[4][2];
#pragma unroll
            for (int mt = 0; mt < 4; mt++) {
                const int r = wm + mt * 16 + g;
                a[mt][0] = *(const uint32_t*)&As[r * AS_H + k + 2 * tig];
                a[mt][1] = *(const uint32_t*)&As[(r + 8) * AS_H + k + 2 * tig];
                a[mt][2] = *(const uint32_t*)&As[r * AS_H + k + 2 * tig + 8];
                a[mt][3] = *(const uint32_t*)&As[(r + 8) * AS_H + k + 2 * tig + 8];
            }
#pragma unroll
            for (int nt = 0; nt < 4; nt++) {
                const int c = wn + nt * 8 + g;
                b[nt][0] = *(const uint32_t*)&Bs[c * BS_H + k + 2 * tig];
                b[nt][1] = *(const uint32_t*)&Bs[c * BS_H + k + 2 * tig + 8];
            }
#pragma unroll
            for (int mt = 0; mt < 4; mt++)
#pragma unroll
                for (int nt = 0; nt < 4; nt++)
                    mma_f16(acc[mt][nt], a[mt], b[nt]);
        }

        __syncthreads();
        if (kt < 31) {
#pragma unroll
            for (int i = 0; i < 4; i++) {
                uint2 p = make_uint2(packh2(ra[i].x, ra[i].y), packh2(ra[i].z, ra[i].w));
                *(uint2*)&As[(arow + i * 32) * AS_H + ac4] = p;
            }
#pragma unroll
            for (int i = 0; i < 2; i++)
                *(uint4*)&Bs[(brow + i * 64) * BS_H + bseg] = rb[i];
            __syncthreads();
        }
    }

    // Epilogue
#pragma unroll
    for (int mt = 0; mt < 4; mt++) {
        const int r = m0 + wm + mt * 16 + g;
#pragma unroll
        for (int nt = 0; nt < 4; nt++) {
            const int c = n0 + wn + nt * 8 + 2 * tig;
            const float b0 = bias[c], b1 = bias[c + 1];
            float2 v0 = make_float2(acc[mt][nt][0] + b0, acc[mt][nt][1] + b1);  // row r
            float2 v1 = make_float2(acc[mt][nt][2] + b0, acc[mt][nt][3] + b1);  // row r+8
            if (MODE == 0) {
                const int h = c >> 6, dd = c & 63;
                const int b0i = r >> 11, tt0 = r & (T_ - 1);
                *(float2*)&out[(((size_t)(b0i * H_ + h) * T_ + tt0) << 6) + dd] = v0;
                const int r1 = r + 8;
                const int b1i = r1 >> 11, tt1 = r1 & (T_ - 1);
                *(float2*)&out[(((size_t)(b1i * H_ + h) * T_ + tt1) << 6) + dd] = v1;
            } else {
                *(float2*)&out[(size_t)r * D_ + c] = v0;
                *(float2*)&out[(size_t)(r + 8) * D_ + c] = v1;
            }
        }
    }
}

__global__ void __launch_bounds__(256) qkv_kernel(
    const float* __restrict__ x,
    const float* __restrict__ bq, const float* __restrict__ bk,
    const float* __restrict__ bv)
{
    const int z = blockIdx.z;
    const __half* Wt = g_wth + (size_t)z * D_ * D_;
    const float* bias = z == 0 ? bq : z == 1 ? bk : bv;
    float* out = z == 0 ? g_q : z == 1 ? g_k : g_v;
    gemm_f16<0>(x, Wt, bias, out);
}

__global__ void __launch_bounds__(256) oproj_kernel(
    const float* __restrict__ bo, float* __restrict__ out)
{
    gemm_f16<1>(g_ctx, g_wth + (size_t)3 * D_ * D_, bo, out);
}

// ---------------------------------------------------------------------------
// Flash attention, fp16 MMA. Block: 128 queries x one (b,h); 8 warps,
// warp owns 16 query rows. 64-key KV tiles. Online softmax in fp32 registers.
// smem halves: Ps[128][72], Ks[64][72] ([key][d]), Vs[64][72] ([d][key]!)
// Q staged as float in the Ps/Ks/Vs region before the kv loop starts.
// ---------------------------------------------------------------------------
#define PS_H 72
#define KS_H 72
#define VS_H 72
#define QF_S 68
#define ATTN_SMEM ((128*PS_H + 64*KS_H + 64*VS_H) * 2)   // 36864 B

__global__ void __launch_bounds__(256) attn_kernel()
{
    extern __shared__ __half smh[];
    __half* Ps = smh;                    // 128*72
    __half* Ks = smh + 128 * PS_H;       // 64*72  [key][d]
    __half* Vs = Ks  + 64 * KS_H;        // 64*72  [d][key] (transposed)
    float*  Qf = (float*)smh;            // Q float staging (dies at first kv fill)

    const int t    = threadIdx.x;
    const int lane = t & 31;
    const int w    = t >> 5;
    const int g    = lane >> 2;
    const int tig  = lane & 3;
    const int qb   = blockIdx.x;
    const int bh   = blockIdx.y;
    const size_t base = (size_t)bh * T_ * 64;
    const int pr   = w * 16 + g;            // warp-local P/Q row (lane's first)
    const int qr   = qb * 128 + pr;         // global query row

    // Stage Q (scaled) as float, then gather fp16 fragments into registers
#pragma unroll
    for (int i = 0; i < 8; i++) {
        const int idx4 = t + i * 256;
        const int r = idx4 >> 4, d4 = (idx4 & 15) * 4;
        float4 q = *(const float4*)(g_q + base + (size_t)(qb * 128 + r) * 64 + d4);
        float* p = &Qf[r * QF_S + d4];
        p[0] = q.x * 0.125f; p[1] = q.y * 0.125f; p[2] = q.z * 0.125f; p[3] = q.w * 0.125f;
    }
    __syncthreads();

    uint32_t qa[4][4];
#pragma unroll
    for (int kk = 0; kk < 4; kk++) {
        const int k = kk * 16;
        qa[kk][0] = packh2(Qf[pr * QF_S + k + 2 * tig],       Qf[pr * QF_S + k + 2 * tig + 1]);
        qa[kk][1] = packh2(Qf[(pr + 8) * QF_S + k + 2 * tig], Qf[(pr + 8) * QF_S + k + 2 * tig + 1]);
        qa[kk][2] = packh2(Qf[pr * QF_S + k + 2 * tig + 8],   Qf[pr * QF_S + k + 2 * tig + 9]);
        qa[kk][3] = packh2(Qf[(pr + 8) * QF_S + k + 2 * tig + 8], Qf[(pr + 8) * QF_S + k + 2 * tig + 9]);
    }
    // (loop-top __syncthreads ensures all warps built qa before Qf is clobbered)

    float o[8][4];
#pragma unroll
    for (int nt = 0; nt < 8; nt++)
#pragma unroll
        for (int i = 0; i < 4; i++) o[nt][i] = 0.f;
    float m0r = neg_inf(), m1r = neg_inf(), l0 = 0.f, l1 = 0.f;

    const int kbmax = 2 * qb + 1;
    for (int kb = 0; kb <= kbmax; kb++) {
        __syncthreads();   // prior Ks/Vs reads done; also protects Qf on kb==0

        // K tile: [key][d] halves, coalesced float4 reads
#pragma unroll
        for (int i = 0; i < 4; i++) {
            const int idx4 = t + i * 256;
            const int r = idx4 >> 4, d4 = (idx4 & 15) * 4;
            float4 kv = *(const float4*)(g_k + base + (size_t)(kb * 64 + r) * 64 + d4);
            *(uint2*)&Ks[r * KS_H + d4] =
                make_uint2(packh2(kv.x, kv.y), packh2(kv.z, kv.w));
        }
        // V tile transposed: [d][key]. Thread covers keys {2*lane, 2*lane+1} at
        // d4 = 4*(w + 8i); stores are half2 at Vs[d][2*lane] -> conflict-free.
#pragma unroll
        for (int i = 0; i < 2; i++) {
            const int d4 = (w + 8 * i) * 4;
            const int k2 = 2 * lane;
            float4 v0 = *(const float4*)(g_v + base + (size_t)(kb * 64 + k2) * 64 + d4);
            float4 v1 = *(const float4*)(g_v + base + (size_t)(kb * 64 + k2 + 1) * 64 + d4);
            *(uint32_t*)&Vs[(d4 + 0) * VS_H + k2] = packh2(v0.x, v1.x);
            *(uint32_t*)&Vs[(d4 + 1) * VS_H + k2] = packh2(v0.y, v1.y);
            *(uint32_t*)&Vs[(d4 + 2) * VS_H + k2] = packh2(v0.z, v1.z);
            *(uint32_t*)&Vs[(d4 + 3) * VS_H + k2] = packh2(v0.w, v1.w);
        }
        __syncthreads();

        // S = Q K^T  (warp: 16 x 64), 4 k16 steps x 8 n-tiles
        float s[8][4];
#pragma unroll
        for (int nt = 0; nt < 8; nt++)
#pragma unroll
            for (int i = 0; i < 4; i++) s[nt][i] = 0.f;
#pragma unroll
        for (int kk = 0; kk < 4; kk++) {
            const int k = kk * 16;
#pragma unroll
            for (int nt = 0; nt < 8; nt++) {
                uint32_t b[2];
                b[0] = *(const uint32_t*)&Ks[(nt * 8 + g) * KS_H + k + 2 * tig];
                b[1] = *(const uint32_t*)&Ks[(nt * 8 + g) * KS_H + k + 2 * tig + 8];
                mma_f16(s[nt], qa[kk], b);
            }
        }

        // Causal mask (diagonal key blocks only)
        if (kb >= 2 * qb) {
            const int r0g = qr, r1g = qr + 8;
#pragma unroll
            for (int nt = 0; nt < 8; nt++) {
                const int j0 = kb * 64 + nt * 8 + 2 * tig;
                if (j0 > r0g)     s[nt][0] = neg_inf();
                if (j0 + 1 > r0g) s[nt][1] = neg_inf();
                if (j0 > r1g)     s[nt][2] = neg_inf();
                if (j0 + 1 > r1g) s[nt][3] = neg_inf();
            }
        }

        // Online softmax (rows g and g+8; 4-lane shfl groups share a row)
        float mx0 = neg_inf(), mx1 = neg_inf();
#pragma unroll
        for (int nt = 0; nt < 8; nt++) {
            mx0 = fmaxf(mx0, fmaxf(s[nt][0], s[nt][1]));
            mx1 = fmaxf(mx1, fmaxf(s[nt][2], s[nt][3]));
        }
        mx0 = fmaxf(mx0, __shfl_xor_sync(0xffffffffu, mx0, 1));
        mx0 = fmaxf(mx0, __shfl_xor_sync(0xffffffffu, mx0, 2));
        mx1 = fmaxf(mx1, __shfl_xor_sync(0xffffffffu, mx1, 1));
        mx1 = fmaxf(mx1, __shfl_xor_sync(0xffffffffu, mx1, 2));

        const float mn0 = fmaxf(m0r, mx0), mn1 = fmaxf(m1r, mx1);
        const float a0 = __expf(m0r - mn0), a1 = __expf(m1r - mn1);
        m0r = mn0; m1r = mn1;

        float rs0 = 0.f, rs1 = 0.f;
#pragma unroll
        for (int nt = 0; nt < 8; nt++) {
            s[nt][0] = __expf(s[nt][0] - mn0);
            s[nt][1] = __expf(s[nt][1] - mn0);
            s[nt][2] = __expf(s[nt][2] - mn1);
            s[nt][3] = __expf(s[nt][3] - mn1);
            rs0 += s[nt][0] + s[nt][1];
            rs1 += s[nt][2] + s[nt][3];
        }
        rs0 += __shfl_xor_sync(0xffffffffu, rs0, 1);
        rs0 += __shfl_xor_sync(0xffffffffu, rs0, 2);
        rs1 += __shfl_xor_sync(0xffffffffu, rs1, 1);
        rs1 += __shfl_xor_sync(0xffffffffu, rs1, 2);
        l0 = l0 * a0 + rs0;
        l1 = l1 * a1 + rs1;

#pragma unroll
        for (int nt = 0; nt < 8; nt++) {
            o[nt][0] *= a0; o[nt][1] *= a0;
            o[nt][2] *= a1; o[nt][3] *= a1;
        }

        // P -> smem fp16 (warp-private rows)
#pragma unroll
        for (int nt = 0; nt < 8; nt++) {
            *(uint32_t*)&Ps[pr * PS_H + nt * 8 + 2 * tig]       = packh2(s[nt][0], s[nt][1]);
            *(uint32_t*)&Ps[(pr + 8) * PS_H + nt * 8 + 2 * tig] = packh2(s[nt][2], s[nt][3]);
        }
        __syncwarp();

        // O += P V : 4 k16 steps x 8 n-tiles (V^T resident as [d][key])
#pragma unroll
        for (int kk = 0; kk < 4; kk++) {
            const int k = kk * 16;
            uint32_t pa[4];
            pa[0] = *(const uint32_t*)&Ps[pr * PS_H + k + 2 * tig];
            pa[1] = *(const uint32_t*)&Ps[(pr + 8) * PS_H + k + 2 * tig];
            pa[2] = *(const uint32_t*)&Ps[pr * PS_H + k + 2 * tig + 8];
            pa[3] = *(const uint32_t*)&Ps[(pr + 8) * PS_H + k + 2 * tig + 8];
#pragma unroll
            for (int nt = 0; nt < 8; nt++) {
                uint32_t b[2];
                b[0] = *(const uint32_t*)&Vs[(nt * 8 + g) * VS_H + k + 2 * tig];
                b[1] = *(const uint32_t*)&Vs[(nt * 8 + g) * VS_H + k + 2 * tig + 8];
                mma_f16(o[nt], pa, b);
            }
        }
    }

    // Epilogue: normalize + write ctx (B,T,D)
    const int bb = bh >> 4, h = bh & 15;
    const float i0 = 1.f / l0, i1 = 1.f / l1;
#pragma unroll
    for (int nt = 0; nt < 8; nt++) {
        const int d = h * 64 + nt * 8 + 2 * tig;
        *(float2*)&g_ctx[(size_t)(bb * T_ + qr) * D_ + d] =
            make_float2(o[nt][0] * i0, o[nt][1] * i0);
        *(float2*)&g_ctx[(size_t)(bb * T_ + qr + 8) * D_ + d] =
            make_float2(o[nt][2] * i1, o[nt][3] * i1);
    }
}

// ---------------------------------------------------------------------------
extern "C" void kernel_launch(void* const* d_in, const int* in_sizes, int n_in,
                              void* d_out, int out_size)
{
    (void)in_sizes; (void)n_in; (void)out_size;
    const float* x  = (const float*)d_in[0];
    const float* Wq = (const float*)d_in[1];
    const float* bq = (const float*)d_in[2];
    const float* Wk = (const float*)d_in[3];
    const float* bk = (const float*)d_in[4];
    const float* Wv = (const float*)d_in[5];
    const float* bv = (const float*)d_in[6];
    const float* Wo = (const float*)d_in[7];
    const float* bo = (const float*)d_in[8];
    float* out = (float*)d_out;

    // 0) Transpose + fp16-round all weights
    transpose_w<<<dim3(D_ / 32, D_ / 32, 4), 256>>>(Wq, Wk, Wv, Wo);

    // 1) QKV projections (fp16 warp MMA)
    qkv_kernel<<<dim3(D_ / 128, M_ / 128, 3), 256>>>(x, bq, bk, bv);

    // 2) Flash attention (fp16 warp MMA)
    cudaFuncSetAttribute(attn_kernel,
                         cudaFuncAttributeMaxDynamicSharedMemorySize, ATTN_SMEM);
    attn_kernel<<<dim3(T_ / 128, B_ * H_), 256, ATTN_SMEM>>>();

    // 3) Output projection
    oproj_kernel<<<dim3(D_ / 128, M_ / 128), 256>>>(bo, out);
}

// round 11
// speedup vs baseline: 7.8955x; 1.0379x over previous
#include <cuda_runtime.h>
#include <cuda_fp16.h>
#include <cstdint>

#define B_  4
#define T_  2048
#define D_  1024
#define H_  16
#define M_  (B_*T_)   // 8192

// Scratch (__device__ globals — allocation rules forbid cudaMalloc)
__device__ __half g_xh[(size_t)M_*D_];        // x in fp16
__device__ __half g_qh[(size_t)B_*H_*T_*64];  // (B,H,T,64) fp16, pre-scaled by 1/8
__device__ __half g_kh[(size_t)B_*H_*T_*64];
__device__ __half g_vh[(size_t)B_*H_*T_*64];
__device__ __half g_ctxh[(size_t)M_*D_];      // (B,T,D) fp16
__device__ __half g_wth[(size_t)4*D_*D_];     // W^T fp16: [4][N][K] (Wq pre-scaled 1/8)

__device__ __forceinline__ float neg_inf() { return __int_as_float(0xff800000u); }

__device__ __forceinline__ uint32_t packh2(float x, float y) {
    __half2 h = __floats2half2_rn(x, y);   // x -> lo, y -> hi
    return *(uint32_t*)&h;
}

__device__ __forceinline__ uint32_t smem_u32(const void* p) {
    uint32_t a;
    asm("{ .reg .u64 t; cvta.to.shared.u64 t, %1; cvt.u32.u64 %0, t; }" : "=r"(a) : "l"(p));
    return a;
}

#define CP16(dst, src) \
    asm volatile("cp.async.cg.shared.global [%0], [%1], 16;" :: "r"(dst), "l"(src))
#define CP_COMMIT() asm volatile("cp.async.commit_group;" ::: "memory")
#define CP_WAIT(n)  asm volatile("cp.async.wait_group %0;" :: "n"(n) : "memory")

// D += A*B, m16n8k16 fp16 (fp32 accum).
__device__ __forceinline__ void mma_f16(float* d, const uint32_t* a, const uint32_t* b) {
    asm volatile(
        "mma.sync.aligned.m16n8k16.row.col.f32.f16.f16.f32 "
        "{%0,%1,%2,%3}, {%4,%5,%6,%7}, {%8,%9}, {%0,%1,%2,%3};"
        : "+f"(d[0]), "+f"(d[1]), "+f"(d[2]), "+f"(d[3])
        : "r"(a[0]), "r"(a[1]), "r"(a[2]), "r"(a[3]), "r"(b[0]), "r"(b[1]));
}

// ---------------------------------------------------------------------------
// x -> fp16  (8M elems, 8 per thread)
// ---------------------------------------------------------------------------
__global__ void __launch_bounds__(256) convert_x(const float* __restrict__ x)
{
    const size_t i = ((size_t)blockIdx.x * 256 + threadIdx.x) * 8;
    float4 a = *(const float4*)(x + i);
    float4 b = *(const float4*)(x + i + 4);
    uint4 o;
    o.x = packh2(a.x, a.y); o.y = packh2(a.z, a.w);
    o.z = packh2(b.x, b.y); o.w = packh2(b.z, b.w);
    *(uint4*)(g_xh + i) = o;
}

// ---------------------------------------------------------------------------
// Weight transpose + fp16 round: g_wth[g][n][k] = half(W_g[k][n]) (*0.125 for Wq)
// ---------------------------------------------------------------------------
__global__ void __launch_bounds__(256) transpose_w(
    const float* __restrict__ W0, const float* __restrict__ W1,
    const float* __restrict__ W2, const float* __restrict__ W3)
{
    __shared__ float tile[32][33];
    const int z = blockIdx.z;
    const float* W = z == 0 ? W0 : z == 1 ? W1 : z == 2 ? W2 : W3;
    const float sc = (z == 0) ? 0.125f : 1.f;
    __half* out = g_wth + (size_t)z * D_ * D_;
    const int k0 = blockIdx.x * 32, n0 = blockIdx.y * 32;
    const int tx = threadIdx.x & 31, ty = threadIdx.x >> 5;
#pragma unroll
    for (int i = 0; i < 32; i += 8)
        tile[ty + i][tx] = W[(size_t)(k0 + ty + i) * D_ + n0 + tx];
    __syncthreads();
#pragma unroll
    for (int i = 0; i < 32; i += 8)
        out[(size_t)(n0 + ty + i) * D_ + k0 + tx] = __float2half_rn(tile[tx][ty + i] * sc);
}

// ---------------------------------------------------------------------------
// fp16 GEMM w/ cp.async 3-stage pipeline: C[M,1024] = A[M,1024]*W + bias*bscale
// BM=BN=128, BK=32; 8 warps (2x4), warp tile 64x32.
// smem per stage: As 128x40h + Bs 128x40h = 20480 B; 3 stages = 61440 B (dynamic)
// MODE 0: store split-heads fp16 (B,H,T,64); MODE 1: row-major fp32 (M,1024)
// ---------------------------------------------------------------------------
#define GST_H  (128*40)          // halves per operand per stage
#define GST_B  (2*GST_H*2)       // bytes per stage (A+B) = 20480
#define GEMM_DYN (3*GST_B)       // 61440

template<int MODE>
__device__ __forceinline__ void gemm_cp(
    const __half* __restrict__ A, const __half* __restrict__ Wt,
    const float* __restrict__ bias, float bscale, void* __restrict__ outv)
{
    extern __shared__ __half smh[];
    const uint32_t smb = smem_u32(smh);

    const int t    = threadIdx.x;
    const int lane = t & 31;
    const int w    = t >> 5;
    const int g    = lane >> 2;
    const int tig  = lane & 3;
    const int wm   = (w >> 2) * 64;
    const int wn   = (w & 3) * 32;
    const int m0   = blockIdx.y * 128;
    const int n0   = blockIdx.x * 128;

    float acc[4][4][4];
#pragma unroll
    for (int mt = 0; mt < 4; mt++)
#pragma unroll
        for (int nt = 0; nt < 4; nt++)
#pragma unroll
            for (int i = 0; i < 4; i++) acc[mt][nt][i] = 0.f;

    // fill stage s with K-chunk k0: 512 16B chunks per operand, 2 per thread
#define GFILL(s, k0) do { \
        const uint32_t ab = smb + (s) * GST_B; \
_Pragma("unroll") \
        for (int i = 0; i < 2; i++) { \
            const int ci  = t + i * 256; \
            const int row = ci >> 2, seg = (ci & 3) * 8; \
            CP16(ab + row * 80 + seg * 2, A  + (size_t)(m0 + row) * D_ + (k0) + seg); \
            CP16(ab + GST_H * 2 + row * 80 + seg * 2, \
                 Wt + (size_t)(n0 + row) * D_ + (k0) + seg); \
        } \
    } while (0)

    GFILL(0, 0);  CP_COMMIT();
    GFILL(1, 32); CP_COMMIT();

    for (int kt = 0; kt < 32; kt++) {
        const int s = kt % 3;
        if (kt >= 30) CP_WAIT(0); else CP_WAIT(1);
        __syncthreads();
        if (kt + 2 < 32) { GFILL((kt + 2) % 3, (kt + 2) * 32); CP_COMMIT(); }

        const __half* As = smh + s * (2 * GST_H);
        const __half* Bs = As + GST_H;
#pragma unroll
        for (int kk = 0; kk < 2; kk++) {
            const int k = kk * 16;
            uint32_t a[4][4], b[4][2];
#pragma unroll
            for (int mt = 0; mt < 4; mt++) {
                const int r = wm + mt * 16 + g;
                a[mt][0] = *(const uint32_t*)&As[r * 40 + k + 2 * tig];
                a[mt][1] = *(const uint32_t*)&As[(r + 8) * 40 + k + 2 * tig];
                a[mt][2] = *(const uint32_t*)&As[r * 40 + k + 2 * tig + 8];
                a[mt][3] = *(const uint32_t*)&As[(r + 8) * 40 + k + 2 * tig + 8];
            }
#pragma unroll
            for (int nt = 0; nt < 4; nt++) {
                const int c = wn + nt * 8 + g;
                b[nt][0] = *(const uint32_t*)&Bs[c * 40 + k + 2 * tig];
                b[nt][1] = *(const uint32_t*)&Bs[c * 40 + k + 2 * tig + 8];
            }
#pragma unroll
            for (int mt = 0; mt < 4; mt++)
#pragma unroll
                for (int nt = 0; nt < 4; nt++)
                    mma_f16(acc[mt][nt], a[mt], b[nt]);
        }
        __syncthreads();
    }
#undef GFILL

    // Epilogue
#pragma unroll
    for (int mt = 0; mt < 4; mt++) {
        const int r = m0 + wm + mt * 16 + g;
#pragma unroll
        for (int nt = 0; nt < 4; nt++) {
            const int c = n0 + wn + nt * 8 + 2 * tig;
            const float b0 = bias[c] * bscale, b1 = bias[c + 1] * bscale;
            const float v00 = acc[mt][nt][0] + b0, v01 = acc[mt][nt][1] + b1;  // row r
            const float v10 = acc[mt][nt][2] + b0, v11 = acc[mt][nt][3] + b1;  // row r+8
            if (MODE == 0) {
                __half* out = (__half*)outv;
                const int h = c >> 6, dd = c & 63;
                const int b0i = r >> 11, tt0 = r & (T_ - 1);
                *(uint32_t*)&out[(((size_t)(b0i * H_ + h) * T_ + tt0) << 6) + dd] =
                    packh2(v00, v01);
                const int r1 = r + 8;
                const int b1i = r1 >> 11, tt1 = r1 & (T_ - 1);
                *(uint32_t*)&out[(((size_t)(b1i * H_ + h) * T_ + tt1) << 6) + dd] =
                    packh2(v10, v11);
            } else {
                float* out = (float*)outv;
                *(float2*)&out[(size_t)r * D_ + c] = make_float2(v00, v01);
                *(float2*)&out[(size_t)(r + 8) * D_ + c] = make_float2(v10, v11);
            }
        }
    }
}

__global__ void __launch_bounds__(256) qkv_kernel(
    const float* __restrict__ bq, const float* __restrict__ bk,
    const float* __restrict__ bv)
{
    const int z = blockIdx.z;
    const __half* Wt = g_wth + (size_t)z * D_ * D_;
    const float* bias = z == 0 ? bq : z == 1 ? bk : bv;
    __half* out = z == 0 ? g_qh : z == 1 ? g_kh : g_vh;
    gemm_cp<0>(g_xh, Wt, bias, z == 0 ? 0.125f : 1.f, out);
}

__global__ void __launch_bounds__(256) oproj_kernel(
    const float* __restrict__ bo, float* __restrict__ out)
{
    gemm_cp<1>(g_ctxh, g_wth + (size_t)3 * D_ * D_, bo, 1.f, out);
}

// ---------------------------------------------------------------------------
// Flash attention, fp16 MMA, fp16 I/O. Block: 128 queries x one (b,h); 8 warps.
// smem halves: Ps[128][72] (Q staged here first), Ks[64][72], Vs[64][72] ([d][key])
// ---------------------------------------------------------------------------
#define PS_H 72
#define KS_H 72
#define VS_H 72
#define ATTN_SMEM ((128*PS_H + 64*KS_H + 64*VS_H) * 2)   // 36864 B

__global__ void __launch_bounds__(256) attn_kernel()
{
    extern __shared__ __half smh[];
    __half* Ps = smh;                    // 128*72 (Q staging, then P)
    __half* Ks = smh + 128 * PS_H;       // 64*72  [key][d]
    __half* Vs = Ks  + 64 * KS_H;        // 64*72  [d][key] (transposed)

    const int t    = threadIdx.x;
    const int lane = t & 31;
    const int w    = t >> 5;
    const int g    = lane >> 2;
    const int tig  = lane & 3;
    const int qb   = blockIdx.x;
    const int bh   = blockIdx.y;
    const size_t base = (size_t)bh * T_ * 64;
    const int pr   = w * 16 + g;            // warp-local row
    const int qr   = qb * 128 + pr;         // global query row

    // Stage Q (already scaled, fp16): 128 rows x 8 chunks of 8 halves
#pragma unroll
    for (int i = 0; i < 4; i++) {
        const int idx = t + i * 256;
        const int r = idx >> 3, seg = (idx & 7) * 8;
        *(uint4*)&Ps[r * PS_H + seg] =
            *(const uint4*)(g_qh + base + (size_t)(qb * 128 + r) * 64 + seg);
    }
    __syncthreads();

    uint32_t qa[4][4];
#pragma unroll
    for (int kk = 0; kk < 4; kk++) {
        const int k = kk * 16;
        qa[kk][0] = *(const uint32_t*)&Ps[pr * PS_H + k + 2 * tig];
        qa[kk][1] = *(const uint32_t*)&Ps[(pr + 8) * PS_H + k + 2 * tig];
        qa[kk][2] = *(const uint32_t*)&Ps[pr * PS_H + k + 2 * tig + 8];
        qa[kk][3] = *(const uint32_t*)&Ps[(pr + 8) * PS_H + k + 2 * tig + 8];
    }

    float o[8][4];
#pragma unroll
    for (int nt = 0; nt < 8; nt++)
#pragma unroll
        for (int i = 0; i < 4; i++) o[nt][i] = 0.f;
    float m0r = neg_inf(), m1r = neg_inf(), l0 = 0.f, l1 = 0.f;

    const int kbmax = 2 * qb + 1;
    for (int kb = 0; kb <= kbmax; kb++) {
        __syncthreads();   // prior Ks/Vs reads done (kb==0: all warps did qa gather)

        // K tile copy: 64 rows x 8 chunks (fp16 direct)
#pragma unroll
        for (int i = 0; i < 2; i++) {
            const int idx = t + i * 256;
            const int r = idx >> 3, seg = (idx & 7) * 8;
            *(uint4*)&Ks[r * KS_H + seg] =
                *(const uint4*)(g_kh + base + (size_t)(kb * 64 + r) * 64 + seg);
        }
        // V tile transposed [d][key]: thread covers keys {2*lane,2*lane+1}, d4=(w+8i)*4
#pragma unroll
        for (int i = 0; i < 2; i++) {
            const int d4 = (w + 8 * i) * 4;
            const int k2 = 2 * lane;
            uint2 u0 = *(const uint2*)(g_vh + base + (size_t)(kb * 64 + k2) * 64 + d4);
            uint2 u1 = *(const uint2*)(g_vh + base + (size_t)(kb * 64 + k2 + 1) * 64 + d4);
            const __half* h0 = (const __half*)&u0;
            const __half* h1 = (const __half*)&u1;
#pragma unroll
            for (int j = 0; j < 4; j++) {
                __half2 p = __halves2half2(h0[j], h1[j]);
                *(uint32_t*)&Vs[(d4 + j) * VS_H + k2] = *(uint32_t*)&p;
            }
        }
        __syncthreads();

        // S = Q K^T  (warp: 16 x 64)
        float s[8][4];
#pragma unroll
        for (int nt = 0; nt < 8; nt++)
#pragma unroll
            for (int i = 0; i < 4; i++) s[nt][i] = 0.f;
#pragma unroll
        for (int kk = 0; kk < 4; kk++) {
            const int k = kk * 16;
#pragma unroll
            for (int nt = 0; nt < 8; nt++) {
                uint32_t b[2];
                b[0] = *(const uint32_t*)&Ks[(nt * 8 + g) * KS_H + k + 2 * tig];
                b[1] = *(const uint32_t*)&Ks[(nt * 8 + g) * KS_H + k + 2 * tig + 8];
                mma_f16(s[nt], qa[kk], b);
            }
        }

        // Causal mask (diagonal key blocks only)
        if (kb >= 2 * qb) {
            const int r0g = qr, r1g = qr + 8;
#pragma unroll
            for (int nt = 0; nt < 8; nt++) {
                const int j0 = kb * 64 + nt * 8 + 2 * tig;
                if (j0 > r0g)     s[nt][0] = neg_inf();
                if (j0 + 1 > r0g) s[nt][1] = neg_inf();
                if (j0 > r1g)     s[nt][2] = neg_inf();
                if (j0 + 1 > r1g) s[nt][3] = neg_inf();
            }
        }

        // Online softmax (rows g and g+8; 4-lane shfl groups share a row)
        float mx0 = neg_inf(), mx1 = neg_inf();
#pragma unroll
        for (int nt = 0; nt < 8; nt++) {
            mx0 = fmaxf(mx0, fmaxf(s[nt][0], s[nt][1]));
            mx1 = fmaxf(mx1, fmaxf(s[nt][2], s[nt][3]));
        }
        mx0 = fmaxf(mx0, __shfl_xor_sync(0xffffffffu, mx0, 1));
        mx0 = fmaxf(mx0, __shfl_xor_sync(0xffffffffu, mx0, 2));
        mx1 = fmaxf(mx1, __shfl_xor_sync(0xffffffffu, mx1, 1));
        mx1 = fmaxf(mx1, __shfl_xor_sync(0xffffffffu, mx1, 2));

        const float mn0 = fmaxf(m0r, mx0), mn1 = fmaxf(m1r, mx1);
        const float a0 = __expf(m0r - mn0), a1 = __expf(m1r - mn1);
        m0r = mn0; m1r = mn1;

        float rs0 = 0.f, rs1 = 0.f;
#pragma unroll
        for (int nt = 0; nt < 8; nt++) {
            s[nt][0] = __expf(s[nt][0] - mn0);
            s[nt][1] = __expf(s[nt][1] - mn0);
            s[nt][2] = __expf(s[nt][2] - mn1);
            s[nt][3] = __expf(s[nt][3] - mn1);
            rs0 += s[nt][0] + s[nt][1];
            rs1 += s[nt][2] + s[nt][3];
        }
        rs0 += __shfl_xor_sync(0xffffffffu, rs0, 1);
        rs0 += __shfl_xor_sync(0xffffffffu, rs0, 2);
        rs1 += __shfl_xor_sync(0xffffffffu, rs1, 1);
        rs1 += __shfl_xor_sync(0xffffffffu, rs1, 2);
        l0 = l0 * a0 + rs0;
        l1 = l1 * a1 + rs1;

#pragma unroll
        for (int nt = 0; nt < 8; nt++) {
            o[nt][0] *= a0; o[nt][1] *= a0;
            o[nt][2] *= a1; o[nt][3] *= a1;
        }

        // P -> smem fp16 (warp-private rows)
#pragma unroll
        for (int nt = 0; nt < 8; nt++) {
            *(uint32_t*)&Ps[pr * PS_H + nt * 8 + 2 * tig]       = packh2(s[nt][0], s[nt][1]);
            *(uint32_t*)&Ps[(pr + 8) * PS_H + nt * 8 + 2 * tig] = packh2(s[nt][2], s[nt][3]);
        }
        __syncwarp();

        // O += P V  (V^T resident as [d][key])
#pragma unroll
        for (int kk = 0; kk < 4; kk++) {
            const int k = kk * 16;
            uint32_t pa[4];
            pa[0] = *(const uint32_t*)&Ps[pr * PS_H + k + 2 * tig];
            pa[1] = *(const uint32_t*)&Ps[(pr + 8) * PS_H + k + 2 * tig];
            pa[2] = *(const uint32_t*)&Ps[pr * PS_H + k + 2 * tig + 8];
            pa[3] = *(const uint32_t*)&Ps[(pr + 8) * PS_H + k + 2 * tig + 8];
#pragma unroll
            for (int nt = 0; nt < 8; nt++) {
                uint32_t b[2];
                b[0] = *(const uint32_t*)&Vs[(nt * 8 + g) * VS_H + k + 2 * tig];
                b[1] = *(const uint32_t*)&Vs[(nt * 8 + g) * VS_H + k + 2 * tig + 8];
                mma_f16(o[nt], pa, b);
            }
        }
    }

    // Epilogue: normalize + write ctx fp16 (B,T,D)
    const int bb = bh >> 4, h = bh & 15;
    const float i0 = 1.f / l0, i1 = 1.f / l1;
#pragma unroll
    for (int nt = 0; nt < 8; nt++) {
        const int d = h * 64 + nt * 8 + 2 * tig;
        *(uint32_t*)&g_ctxh[(size_t)(bb * T_ + qr) * D_ + d] =
            packh2(o[nt][0] * i0, o[nt][1] * i0);
        *(uint32_t*)&g_ctxh[(size_t)(bb * T_ + qr + 8) * D_ + d] =
            packh2(o[nt][2] * i1, o[nt][3] * i1);
    }
}

// ---------------------------------------------------------------------------
extern "C" void kernel_launch(void* const* d_in, const int* in_sizes, int n_in,
                              void* d_out, int out_size)
{
    (void)in_sizes; (void)n_in; (void)out_size;
    const float* x  = (const float*)d_in[0];
    const float* Wq = (const float*)d_in[1];
    const float* bq = (const float*)d_in[2];
    const float* Wk = (const float*)d_in[3];
    const float* bk = (const float*)d_in[4];
    const float* Wv = (const float*)d_in[5];
    const float* bv = (const float*)d_in[6];
    const float* Wo = (const float*)d_in[7];
    const float* bo = (const float*)d_in[8];
    float* out = (float*)d_out;

    // 0) Precompute fp16 operands
    convert_x<<<M_ * D_ / (256 * 8), 256>>>(x);
    transpose_w<<<dim3(D_ / 32, D_ / 32, 4), 256>>>(Wq, Wk, Wv, Wo);

    // 1) QKV projections (fp16 MMA, cp.async pipeline)
    cudaFuncSetAttribute(qkv_kernel, cudaFuncAttributeMaxDynamicSharedMemorySize, GEMM_DYN);
    qkv_kernel<<<dim3(D_ / 128, M_ / 128, 3), 256, GEMM_DYN>>>(bq, bk, bv);

    // 2) Flash attention
    cudaFuncSetAttribute(attn_kernel, cudaFuncAttributeMaxDynamicSharedMemorySize, ATTN_SMEM);
    attn_kernel<<<dim3(T_ / 128, B_ * H_), 256, ATTN_SMEM>>>();

    // 3) Output projection
    cudaFuncSetAttribute(oproj_kernel, cudaFuncAttributeMaxDynamicSharedMemorySize, GEMM_DYN);
    oproj_kernel<<<dim3(D_ / 128, M_ / 128), 256, GEMM_DYN>>>(bo, out);
}